// round 15
// baseline (speedup 1.0000x reference)
#include <cuda_runtime.h>
#include <cuda_fp16.h>
#include <math.h>
#include <stdint.h>

#define HH 108
#define HP 64               // padded u32 pitch for split rows (256B)
#define ZP 54               // u32 pitch for packed fp16 z rows
#define NCAP 100000
#define ECAP 1600000
#define GCAP 1024
#define SC_T 256
#define SC_I 8
#define SC_CH (SC_T * SC_I)
#define PGRID 444           // persistent grid: 148 SM x 3 CTAs

// -------- device scratch --------
__device__ float    g_h[NCAP * HH];
__device__ float    g_z[NCAP * HH];    // reused as packed fp16 z (u32, pitch ZP)
__device__ uint32_t g_hh[NCAP * HP];
__device__ uint32_t g_hl[NCAP * HP];
__device__ uint32_t g_ch[NCAP * HP];   // also scratch for split nodes_feat before layer 0
__device__ uint32_t g_cl[NCAP * HP];
__device__ uint32_t g_wh[65536];
__device__ int   g_deg[NCAP];
__device__ int   g_rowptr[NCAP + 1];
__device__ int   g_cursor[NCAP];
__device__ int   g_col[ECAP];
__device__ int   g_part[256];

// ================= helpers =================
__device__ __forceinline__ uint32_t smem_to_u32(const void* smem_ptr) {
    uint32_t addr;
    asm("{ .reg .u64 tmp; cvta.to.shared.u64 tmp, %1; cvt.u32.u64 %0, tmp; }"
        : "=r"(addr) : "l"(smem_ptr));
    return addr;
}
__device__ __forceinline__ void ldm_x4(uint32_t* r, uint32_t addr) {
    asm volatile("ldmatrix.sync.aligned.m8n8.x4.shared.b16 {%0,%1,%2,%3}, [%4];"
        : "=r"(r[0]), "=r"(r[1]), "=r"(r[2]), "=r"(r[3]) : "r"(addr));
}
__device__ __forceinline__ void ldm_x2(uint32_t* r, uint32_t addr) {
    asm volatile("ldmatrix.sync.aligned.m8n8.x2.shared.b16 {%0,%1}, [%2];"
        : "=r"(r[0]), "=r"(r[1]) : "r"(addr));
}
__device__ __forceinline__ void mma_fp16(float* c, const uint32_t* a, const uint32_t* b) {
    asm volatile(
        "mma.sync.aligned.m16n8k16.row.col.f32.f16.f16.f32 "
        "{%0,%1,%2,%3}, {%4,%5,%6,%7}, {%8,%9}, {%0,%1,%2,%3};"
        : "+f"(c[0]), "+f"(c[1]), "+f"(c[2]), "+f"(c[3])
        : "r"(a[0]), "r"(a[1]), "r"(a[2]), "r"(a[3]), "r"(b[0]), "r"(b[1]));
}
__device__ __forceinline__ void cp16(uint32_t dst, const void* src, int sz) {
    asm volatile("cp.async.cg.shared.global [%0], [%1], 16, %2;"
                 :: "r"(dst), "l"(src), "r"(sz) : "memory");
}
#define CP_COMMIT() asm volatile("cp.async.commit_group;" ::: "memory")
#define CP_WAIT0()  asm volatile("cp.async.wait_group 0;" ::: "memory")
#define SWZ128(b) ((b) ^ (((b) >> 3) & 0x70))

__device__ __forceinline__ void split2h(float x, float y, uint32_t& hp, uint32_t& lp) {
    __half hx = __float2half_rn(x), hy = __float2half_rn(y);
    float lx = x - __half2float(hx), ly = y - __half2float(hy);
    hp = ((uint32_t)__half_as_ushort(hy) << 16) | __half_as_ushort(hx);
    lp = ((uint32_t)__half_as_ushort(__float2half_rn(ly)) << 16)
       | __half_as_ushort(__float2half_rn(lx));
}
__device__ __forceinline__ uint32_t pack_h(float x, float y) {
    return ((uint32_t)__half_as_ushort(__float2half_rn(y)) << 16)
         | __half_as_ushort(__float2half_rn(x));
}

// ================= smem layout: 64-row tiles, double-buffered =================
#define SM_BIAS 0        // 112 floats
#define SM_NRM  512      // 64 x 2 floats
#define SM_AH   1024     // 64 x 128B = 8192
#define SM_AL   (SM_AH + 8192)
#define SM_BH   (SM_AL + 8192)   // 112 x 128B = 14336
#define STG     30720
#define SM_TOTAL (1024 + 2 * STG)   // 62464 -> 3 CTAs/SM

// ================= weight prep =================
__global__ void prep_w(const float* __restrict__ W_emb, int Kemb, int KPe,
                       const float* __restrict__ pool_W,
                       const float* __restrict__ app_W, int n_layers, int total) {
    int idx = blockIdx.x * blockDim.x + threadIdx.x;
    if (idx >= total) return;
    const float* Wp = 0;
    int K = 0, KP = 0, rel = idx, off = 0, is_app = 0;
    int sz = 112 * (KPe >> 1);
    if (idx < sz) { Wp = W_emb; K = Kemb; KP = KPe; rel = idx; }
    else {
        off = sz;
        for (int l = 0; l < n_layers && !Wp; l++) {
            if (idx < off + 112 * 64) { Wp = pool_W + l * HH * HH; K = HH; KP = 128; rel = idx - off; }
            off += 112 * 64;
        }
        for (int l = 0; l < n_layers && !Wp; l++) {
            if (idx < off + 112 * 128) { Wp = app_W + l * 2 * HH * HH; K = 2 * HH; KP = 256; rel = idx - off; is_app = 1; }
            off += 112 * 128;
        }
        if (!Wp) return;
    }
    int nn = rel / (KP >> 1);
    int kp = rel - nn * (KP >> 1);
    float w[2];
#pragma unroll
    for (int q = 0; q < 2; q++) {
        int k = kp * 2 + q;
        int kk, valid;
        if (is_app) {
            if (k < 128) { kk = k; valid = (k < HH); }
            else { kk = HH + (k - 128); valid = (k - 128 < HH); }
        } else { kk = k; valid = (k < K); }
        w[q] = (nn < HH && valid) ? Wp[kk * HH + nn] : 0.f;
    }
    g_wh[idx] = pack_h(w[0], w[1]);
}

// ================= split nodes_feat into (xh, xl), pitch KPe/2 ================
__global__ void prep_x(const float* __restrict__ X, int in_dim, int KPe,
                       uint32_t* __restrict__ xh, uint32_t* __restrict__ xl, int total) {
    int idx = blockIdx.x * blockDim.x + threadIdx.x;
    if (idx >= total) return;
    int pu = KPe >> 1;
    int row = idx / pu;
    int kp = idx - row * pu;
    int k0 = kp * 2;
    float x0 = (k0 < in_dim) ? X[(size_t)row * in_dim + k0] : 0.f;
    float x1 = (k0 + 1 < in_dim) ? X[(size_t)row * in_dim + k0 + 1] : 0.f;
    uint32_t hp, lp;
    split2h(x0, x1, hp, lp);
    xh[idx] = hp;
    xl[idx] = lp;
}

// ================= CSR build =================
__global__ void zero_deg_kernel(int n) {
    int i = blockIdx.x * blockDim.x + threadIdx.x;
    if (i < n) g_deg[i] = 0;
}
__global__ void hist_kernel(const int* __restrict__ dst, int e) {
    int i = blockIdx.x * blockDim.x + threadIdx.x;
    if (i < e) atomicAdd(&g_deg[dst[i]], 1);
}
__global__ void scan1_kernel(int n) {
    __shared__ int sh[SC_T];
    int t = threadIdx.x, b = blockIdx.x;
    int base = b * SC_CH + t * SC_I;
    int v[SC_I];
    int run = 0;
#pragma unroll
    for (int j = 0; j < SC_I; j++) {
        int idx = base + j;
        int x = (idx < n) ? g_deg[idx] : 0;
        run += x;
        v[j] = run;
    }
    sh[t] = run;
    __syncthreads();
    for (int off = 1; off < SC_T; off <<= 1) {
        int x = (t >= off) ? sh[t - off] : 0;
        __syncthreads();
        sh[t] += x;
        __syncthreads();
    }
    int excl = sh[t] - run;
#pragma unroll
    for (int j = 0; j < SC_I; j++) {
        int idx = base + j;
        if (idx < n) g_rowptr[1 + idx] = excl + v[j];
    }
    if (t == SC_T - 1) g_part[b] = sh[t];
}
__global__ void scan2_kernel(int nb) {
    __shared__ int sh[256];
    int t = threadIdx.x;
    int v = (t < nb) ? g_part[t] : 0;
    sh[t] = v;
    __syncthreads();
    for (int off = 1; off < 256; off <<= 1) {
        int x = (t >= off) ? sh[t - off] : 0;
        __syncthreads();
        sh[t] += x;
        __syncthreads();
    }
    if (t < nb) g_part[t] = sh[t] - v;
}
__global__ void scan3_kernel(int n) {
    int idx = blockIdx.x * blockDim.x + threadIdx.x;
    if (idx < n) {
        int val = g_rowptr[1 + idx] + g_part[idx / SC_CH];
        g_rowptr[1 + idx] = val;
        if (idx + 1 < n) g_cursor[idx + 1] = val;
    }
    if (idx == 0) { g_rowptr[0] = 0; g_cursor[0] = 0; }
}
__global__ void fillcsr_kernel(const int* __restrict__ src, const int* __restrict__ dst, int e) {
    int i = blockIdx.x * blockDim.x + threadIdx.x;
    if (i < e) {
        int d = dst[i];
        int pos = atomicAdd(&g_cursor[d], 1);
        g_col[pos] = src[i];
    }
}

// ================= persistent tensor-core GEMM (split-fp16) ===================
// terms: 2 = Ah@Bh + Al@Bh (full split); 1 = Ah@Bh only (for z, whose output is
// fp16-quantized anyway).
__global__ __launch_bounds__(256, 3)
void gemm_tc(const uint32_t* __restrict__ Ah1, const uint32_t* __restrict__ Al1,
             const uint32_t* __restrict__ Ah2, const uint32_t* __restrict__ Al2,
             int NC1, int apitch,
             const uint32_t* __restrict__ Wh, int wstride,
             const float* __restrict__ bias,
             float* __restrict__ out,
             const uint32_t* __restrict__ resH, const uint32_t* __restrict__ resL,
             uint32_t* __restrict__ outH, uint32_t* __restrict__ outL,
             int n, int K, int mode, int terms) {
    extern __shared__ char sm[];
    const uint32_t sb = smem_to_u32(sm);
    const int tid = threadIdx.x;
    const int wid = tid >> 5;
    const int lane = tid & 31;
    float* bias_s = (float*)(sm + SM_BIAS);
    float* nrm_s  = (float*)(sm + SM_NRM);

    if (tid < 112) bias_s[tid] = (tid < HH) ? bias[tid] : 0.f;

    const int rg = wid & 3;
    const int colh = wid >> 2;
    const int warp_r0 = rg * 16;
    const int a_row = warp_r0 + (lane & 15);
    const int a_kb  = (lane >> 4) * 16;
    const int b_row = lane & 7;
    const int b_kb  = ((lane >> 3) & 1) * 16;
    const int NC = K >> 6;
    const int tiles = (n + 63) >> 6;
    const int afill = (terms == 2) ? 1024 : 512;

    auto issue_fill = [&](int row0, int c, int s) {
        const uint32_t* srcH = (c < NC1) ? Ah1 : Ah2;
        const uint32_t* srcL = (c < NC1) ? Al1 : Al2;
        int coff = ((c < NC1) ? c : (c - NC1)) * 32;
        uint32_t base = sb + s * STG;
        for (int idx = tid; idx < afill; idx += 256) {
            int u = idx & 7;
            int row = (idx >> 3) & 63;
            int hi = idx < 512;
            int grow = row0 + row;
            const uint32_t* src = (hi ? srcH : srcL) + (size_t)grow * apitch + coff + u * 4;
            uint32_t dst = base + (hi ? SM_AH : SM_AL) + SWZ128((uint32_t)(row * 128 + u * 16));
            cp16(dst, src, grow < n ? 16 : 0);
        }
        int kc32 = c * 32;
        for (int idx = tid; idx < 896; idx += 256) {
            int u = idx & 7;
            int nn = idx >> 3;
            const uint32_t* src = Wh + nn * wstride + kc32 + u * 4;
            uint32_t dst = base + SM_BH + SWZ128((uint32_t)(nn * 128 + u * 16));
            cp16(dst, src, 16);
        }
    };

    int t = (int)blockIdx.x;
    if (t >= tiles) return;
    int s = 0;
    issue_fill(t * 64, 0, 0);
    CP_COMMIT();

    for (; t < tiles; t += (int)gridDim.x) {
        const int row0 = t * 64;
        float acc[7][4];
#pragma unroll
        for (int nt = 0; nt < 7; nt++)
#pragma unroll
            for (int q = 0; q < 4; q++) acc[nt][q] = 0.f;

        for (int c = 0; c < NC; c++) {
            CP_WAIT0();
            __syncthreads();
            int ntile = (c + 1 < NC) ? t : t + (int)gridDim.x;
            int nch   = (c + 1 < NC) ? c + 1 : 0;
            if (ntile < tiles) {
                issue_fill(ntile * 64, nch, s ^ 1);
                CP_COMMIT();
            }
            uint32_t base = sb + s * STG;
#pragma unroll
            for (int ks = 0; ks < 4; ks++) {
                uint32_t aloc = SWZ128((uint32_t)(a_row * 128 + a_kb + ks * 32));
                uint32_t ah[4], al[4];
                ldm_x4(ah, base + SM_AH + aloc);
                if (terms == 2) ldm_x4(al, base + SM_AL + aloc);
                uint32_t bloc = SWZ128((uint32_t)(b_row * 128 + b_kb + ks * 32));
                uint32_t bh[7][2];
#pragma unroll
                for (int nt = 0; nt < 7; nt++)
                    ldm_x2(bh[nt], base + SM_BH + bloc + (colh * 7 + nt) * 1024);
#pragma unroll
                for (int nt = 0; nt < 7; nt++) {
                    mma_fp16(acc[nt], ah, bh[nt]);
                    if (terms == 2) mma_fp16(acc[nt], al, bh[nt]);
                }
            }
            s ^= 1;
        }

        // ---- epilogue ----
        const int erl = warp_r0 + (lane >> 2);
        const int ec = (lane & 3) * 2;
        const int glo = row0 + erl, ghi = glo + 8;
        float ss0 = 0.f, ss1 = 0.f;
#pragma unroll
        for (int nt = 0; nt < 7; nt++) {
            int col = (colh * 7 + nt) * 8 + ec;
            float b0 = bias_s[col], b1 = bias_s[col + 1];
            acc[nt][0] += b0; acc[nt][1] += b1;
            acc[nt][2] += b0; acc[nt][3] += b1;
            if (mode == 2) {
                ss0 += acc[nt][0] * acc[nt][0] + acc[nt][1] * acc[nt][1];
                ss1 += acc[nt][2] * acc[nt][2] + acc[nt][3] * acc[nt][3];
            }
        }
        float s0 = 1.f, s1 = 1.f;
        if (mode == 2) {
            ss0 += __shfl_xor_sync(0xFFFFFFFFu, ss0, 1);
            ss0 += __shfl_xor_sync(0xFFFFFFFFu, ss0, 2);
            ss1 += __shfl_xor_sync(0xFFFFFFFFu, ss1, 1);
            ss1 += __shfl_xor_sync(0xFFFFFFFFu, ss1, 2);
            if ((lane & 3) == 0) {
                nrm_s[erl * 2 + colh] = ss0;
                nrm_s[(erl + 8) * 2 + colh] = ss1;
            }
            __syncthreads();
            s0 = 1.f / fmaxf(sqrtf(nrm_s[erl * 2] + nrm_s[erl * 2 + 1]), 1e-12f);
            s1 = 1.f / fmaxf(sqrtf(nrm_s[(erl + 8) * 2] + nrm_s[(erl + 8) * 2 + 1]), 1e-12f);
            __syncthreads();
        }
#pragma unroll
        for (int nt = 0; nt < 7; nt++) {
            int col = (colh * 7 + nt) * 8 + ec;
            if (col >= HH) continue;
            float v0 = acc[nt][0], v1 = acc[nt][1], v2 = acc[nt][2], v3 = acc[nt][3];
            if (mode == 3) {
                v0 = fmaxf(v0, 0.f); v1 = fmaxf(v1, 0.f);
                v2 = fmaxf(v2, 0.f); v3 = fmaxf(v3, 0.f);
                uint32_t* zo = (uint32_t*)out;
                if (glo < n) zo[(size_t)glo * ZP + (col >> 1)] = pack_h(v0, v1);
                if (ghi < n) zo[(size_t)ghi * ZP + (col >> 1)] = pack_h(v2, v3);
                continue;
            }
            if (mode == 2) {
                if (glo < n) {
                    uint32_t hp = resH[(size_t)glo * HP + (col >> 1)];
                    uint32_t lp = resL[(size_t)glo * HP + (col >> 1)];
                    float2 fh = __half22float2(*(__half2*)&hp);
                    float2 fl = __half22float2(*(__half2*)&lp);
                    v0 = (fh.x + fl.x) + fmaxf(v0 * s0, 0.f);
                    v1 = (fh.y + fl.y) + fmaxf(v1 * s0, 0.f);
                }
                if (ghi < n) {
                    uint32_t hp = resH[(size_t)ghi * HP + (col >> 1)];
                    uint32_t lp = resL[(size_t)ghi * HP + (col >> 1)];
                    float2 fh = __half22float2(*(__half2*)&hp);
                    float2 fl = __half22float2(*(__half2*)&lp);
                    v2 = (fh.x + fl.x) + fmaxf(v2 * s1, 0.f);
                    v3 = (fh.y + fl.y) + fmaxf(v3 * s1, 0.f);
                }
            }
            if (out) {
                if (glo < n) *(float2*)(out + (size_t)glo * HH + col) = make_float2(v0, v1);
                if (ghi < n) *(float2*)(out + (size_t)ghi * HH + col) = make_float2(v2, v3);
            }
            if (outH) {
                uint32_t hp, lp;
                if (glo < n) {
                    split2h(v0, v1, hp, lp);
                    outH[(size_t)glo * HP + (col >> 1)] = hp;
                    outL[(size_t)glo * HP + (col >> 1)] = lp;
                }
                if (ghi < n) {
                    split2h(v2, v3, hp, lp);
                    outH[(size_t)ghi * HP + (col >> 1)] = hp;
                    outL[(size_t)ghi * HP + (col >> 1)] = lp;
                }
            }
        }
    }
}

// ===== mean aggregation over CSR: z packed fp16 (pitch ZP) -> split c (pitch HP)
__global__ void aggregate_kernel(const uint32_t* __restrict__ zp,
                                 uint32_t* __restrict__ ch, uint32_t* __restrict__ cl, int n) {
    int w = (blockIdx.x * blockDim.x + threadIdx.x) >> 5;
    int lane = threadIdx.x & 31;
    if (w >= n || lane >= 27) return;
    int s = g_rowptr[w], e = g_rowptr[w + 1];
    float a0 = 0.f, a1 = 0.f, a2 = 0.f, a3 = 0.f;
    int i = s;
    for (; i + 7 < e; i += 8) {
        int cc[8];
#pragma unroll
        for (int q = 0; q < 8; q++) cc[q] = g_col[i + q];
        uint2 u[8];
#pragma unroll
        for (int q = 0; q < 8; q++) u[q] = ((const uint2*)(zp + (size_t)cc[q] * ZP))[lane];
#pragma unroll
        for (int q = 0; q < 8; q++) {
            float2 f0 = __half22float2(*(__half2*)&u[q].x);
            float2 f1 = __half22float2(*(__half2*)&u[q].y);
            a0 += f0.x; a1 += f0.y; a2 += f1.x; a3 += f1.y;
        }
    }
    if (i + 3 < e) {
        int cc[4];
#pragma unroll
        for (int q = 0; q < 4; q++) cc[q] = g_col[i + q];
        uint2 u[4];
#pragma unroll
        for (int q = 0; q < 4; q++) u[q] = ((const uint2*)(zp + (size_t)cc[q] * ZP))[lane];
#pragma unroll
        for (int q = 0; q < 4; q++) {
            float2 f0 = __half22float2(*(__half2*)&u[q].x);
            float2 f1 = __half22float2(*(__half2*)&u[q].y);
            a0 += f0.x; a1 += f0.y; a2 += f1.x; a3 += f1.y;
        }
        i += 4;
    }
    for (; i < e; i++) {
        uint2 u0 = ((const uint2*)(zp + (size_t)g_col[i] * ZP))[lane];
        float2 f0 = __half22float2(*(__half2*)&u0.x);
        float2 f1 = __half22float2(*(__half2*)&u0.y);
        a0 += f0.x; a1 += f0.y; a2 += f1.x; a3 += f1.y;
    }
    float inv = 1.f / (float)max(e - s, 1);
    uint32_t hp0, lp0, hp1, lp1;
    split2h(a0 * inv, a1 * inv, hp0, lp0);
    split2h(a2 * inv, a3 * inv, hp1, lp1);
    ch[(size_t)w * HP + lane * 2] = hp0;
    ch[(size_t)w * HP + lane * 2 + 1] = hp1;
    cl[(size_t)w * HP + lane * 2] = lp0;
    cl[(size_t)w * HP + lane * 2 + 1] = lp1;
}

// ================= graph readout: block per graph (gids SORTED) ===============
__global__ void readout_graph(const float* __restrict__ h, const int* __restrict__ gids,
                              float* __restrict__ out, int n) {
    __shared__ float part[8][112];
    const int g = blockIdx.x;
    const int tid = threadIdx.x;
    const int wid = tid >> 5;
    const int lane = tid & 31;
    int lo = 0, hi = n;
    while (lo < hi) { int m = (lo + hi) >> 1; if (gids[m] < g) lo = m + 1; else hi = m; }
    const int start = lo;
    hi = n;
    while (lo < hi) { int m = (lo + hi) >> 1; if (gids[m] < g + 1) lo = m + 1; else hi = m; }
    const int end = lo;

    float a0 = 0.f, a1 = 0.f, a2 = 0.f, a3 = 0.f;
    if (lane < 27) {
        for (int r = start + wid; r < end; r += 8) {
            float4 v = ((const float4*)(h + (size_t)r * HH))[lane];
            a0 += v.x; a1 += v.y; a2 += v.z; a3 += v.w;
        }
        part[wid][lane * 4]     = a0;
        part[wid][lane * 4 + 1] = a1;
        part[wid][lane * 4 + 2] = a2;
        part[wid][lane * 4 + 3] = a3;
    }
    __syncthreads();
    if (tid < HH) {
        float sum = 0.f;
#pragma unroll
        for (int wq = 0; wq < 8; wq++) sum += part[wq][tid];
        out[(size_t)g * HH + tid] = sum / fmaxf((float)(end - start), 1.f);
    }
}

// ================= launch =================
extern "C" void kernel_launch(void* const* d_in, const int* in_sizes, int n_in,
                              void* d_out, int out_size) {
    const float* nodes_feat = (const float*)d_in[0];
    const float* W_emb  = (const float*)d_in[4];
    const float* b_emb  = (const float*)d_in[5];
    const float* pool_W = (const float*)d_in[6];
    const float* pool_b = (const float*)d_in[7];
    const float* app_W  = (const float*)d_in[8];
    const float* app_b  = (const float*)d_in[9];
    const int* src  = (const int*)d_in[10];
    const int* dst  = (const int*)d_in[11];
    const int* gids = (const int*)d_in[12];

    const int n = in_sizes[12];
    const int e = in_sizes[10];
    const int in_dim = in_sizes[4] / HH;
    const int n_layers = in_sizes[6] / (HH * HH);
    const int G = out_size / HH;

    float *hP, *zP;
    uint32_t *hhP, *hlP, *chP, *clP, *whP;
    cudaGetSymbolAddress((void**)&hP, g_h);
    cudaGetSymbolAddress((void**)&zP, g_z);
    cudaGetSymbolAddress((void**)&hhP, g_hh);
    cudaGetSymbolAddress((void**)&hlP, g_hl);
    cudaGetSymbolAddress((void**)&chP, g_ch);
    cudaGetSymbolAddress((void**)&clP, g_cl);
    cudaGetSymbolAddress((void**)&whP, g_wh);

    cudaFuncSetAttribute(gemm_tc, cudaFuncAttributeMaxDynamicSharedMemorySize, SM_TOTAL);

    static cudaStream_t s2 = 0;
    static cudaEvent_t evFork = 0, evJoin = 0;
    if (!s2) {
        cudaStreamCreateWithFlags(&s2, cudaStreamNonBlocking);
        cudaEventCreateWithFlags(&evFork, cudaEventDisableTiming);
        cudaEventCreateWithFlags(&evJoin, cudaEventDisableTiming);
    }

    const int KPe = ((in_dim + 63) / 64) * 64;
    const int u_emb = 112 * (KPe >> 1);
    const int u_pool = 112 * 64;
    const int u_app = 112 * 128;
    const int w_total = u_emb + n_layers * (u_pool + u_app);
    const int x_total = n * (KPe >> 1);

    const int tiles = (n + 63) / 64;
    const int pg = tiles < PGRID ? tiles : PGRID;
    int warp_blocks = ((n * 32) + 255) / 256;

    // ---- fork: CSR build on side stream (depends only on src/dst) ----
    cudaEventRecord(evFork, 0);
    cudaStreamWaitEvent(s2, evFork, 0);
    zero_deg_kernel<<<(n + 255) / 256, 256, 0, s2>>>(n);
    hist_kernel<<<(e + 255) / 256, 256, 0, s2>>>(dst, e);
    int nb = (n + SC_CH - 1) / SC_CH;
    scan1_kernel<<<nb, SC_T, 0, s2>>>(n);
    scan2_kernel<<<1, 256, 0, s2>>>(nb);
    scan3_kernel<<<(n + 255) / 256, 256, 0, s2>>>(n);
    fillcsr_kernel<<<(e + 255) / 256, 256, 0, s2>>>(src, dst, e);
    cudaEventRecord(evJoin, s2);

    // ---- main stream: prep + embedding ----
    prep_w<<<(w_total + 255) / 256, 256>>>(W_emb, in_dim, KPe, pool_W, app_W,
                                           n_layers, w_total);
    prep_x<<<(x_total + 255) / 256, 256>>>(nodes_feat, in_dim, KPe, chP, clP, x_total);
    gemm_tc<<<pg, 256, SM_TOTAL>>>(chP, clP, (const uint32_t*)0, (const uint32_t*)0,
                                   KPe >> 6, KPe >> 1,
                                   whP, KPe >> 1,
                                   b_emb, (float*)0, (const uint32_t*)0, (const uint32_t*)0,
                                   hhP, hlP,
                                   n, KPe, 0, 2);

    bool joined = false;
    for (int l = 0; l < n_layers; l++) {
        const float* pb = pool_b + (size_t)l * HH;
        const float* ab = app_b + (size_t)l * HH;
        const uint32_t* pWh = whP + u_emb + l * u_pool;
        const uint32_t* aWh = whP + u_emb + n_layers * u_pool + l * u_app;

        // z = relu(h @ pool_W + pool_b) -> packed fp16; single-term (z is fp16 anyway)
        gemm_tc<<<pg, 256, SM_TOTAL>>>(hhP, hlP, (const uint32_t*)0, (const uint32_t*)0,
                                       2, HP,
                                       pWh, 64,
                                       pb, zP, (const uint32_t*)0, (const uint32_t*)0,
                                       (uint32_t*)0, (uint32_t*)0,
                                       n, 128, 3, 1);
        if (!joined) { cudaStreamWaitEvent(0, evJoin, 0); joined = true; }
        // c = mean_{u in N(v)} z[u]
        aggregate_kernel<<<warp_blocks, 256>>>((const uint32_t*)zP, chP, clP, n);
        // h = h + relu(l2norm([h|c] @ app_W + app_b)); residual from split h
        int last = (l == n_layers - 1);
        gemm_tc<<<pg, 256, SM_TOTAL>>>(hhP, hlP, chP, clP,
                                       2, HP,
                                       aWh, 128,
                                       ab,
                                       last ? hP : (float*)0,
                                       hhP, hlP,
                                       last ? (uint32_t*)0 : hhP,
                                       last ? (uint32_t*)0 : hlP,
                                       n, 256, 2, 2);
    }

    // ---- readout: one block per graph, no atomics (gids sorted) ----
    readout_graph<<<G, 256>>>(hP, gids, (float*)d_out, n);
}

// round 16
// speedup vs baseline: 1.0317x; 1.0317x over previous
#include <cuda_runtime.h>
#include <cuda_fp16.h>
#include <math.h>
#include <stdint.h>

#define HH 108
#define HP 64               // padded u32 pitch for split rows (256B)
#define ZP 54               // u32 pitch for packed fp16 z rows
#define NCAP 100000
#define ECAP 1600000
#define GCAP 1024
#define SC_T 256
#define SC_I 8
#define SC_CH (SC_T * SC_I)
#define PGRID 444           // persistent grid: 148 SM x 3 CTAs

// -------- device scratch --------
__device__ float    g_h[NCAP * HH];
__device__ float    g_z[NCAP * HH];    // reused as packed fp16 z (u32, pitch ZP)
__device__ uint32_t g_hh[NCAP * HP];
__device__ uint32_t g_hl[NCAP * HP];
__device__ uint32_t g_ch[NCAP * HP];   // also scratch for split nodes_feat before layer 0
__device__ uint32_t g_cl[NCAP * HP];   // used only for split nodes_feat (emb lo)
__device__ uint32_t g_wh[65536];
__device__ int   g_deg[NCAP];
__device__ int   g_rowptr[NCAP + 1];
__device__ int   g_cursor[NCAP];
__device__ int   g_col[ECAP];
__device__ int   g_part[256];

// ================= helpers =================
__device__ __forceinline__ uint32_t smem_to_u32(const void* smem_ptr) {
    uint32_t addr;
    asm("{ .reg .u64 tmp; cvta.to.shared.u64 tmp, %1; cvt.u32.u64 %0, tmp; }"
        : "=r"(addr) : "l"(smem_ptr));
    return addr;
}
__device__ __forceinline__ void ldm_x4(uint32_t* r, uint32_t addr) {
    asm volatile("ldmatrix.sync.aligned.m8n8.x4.shared.b16 {%0,%1,%2,%3}, [%4];"
        : "=r"(r[0]), "=r"(r[1]), "=r"(r[2]), "=r"(r[3]) : "r"(addr));
}
__device__ __forceinline__ void ldm_x2(uint32_t* r, uint32_t addr) {
    asm volatile("ldmatrix.sync.aligned.m8n8.x2.shared.b16 {%0,%1}, [%2];"
        : "=r"(r[0]), "=r"(r[1]) : "r"(addr));
}
__device__ __forceinline__ void mma_fp16(float* c, const uint32_t* a, const uint32_t* b) {
    asm volatile(
        "mma.sync.aligned.m16n8k16.row.col.f32.f16.f16.f32 "
        "{%0,%1,%2,%3}, {%4,%5,%6,%7}, {%8,%9}, {%0,%1,%2,%3};"
        : "+f"(c[0]), "+f"(c[1]), "+f"(c[2]), "+f"(c[3])
        : "r"(a[0]), "r"(a[1]), "r"(a[2]), "r"(a[3]), "r"(b[0]), "r"(b[1]));
}
__device__ __forceinline__ void cp16(uint32_t dst, const void* src, int sz) {
    asm volatile("cp.async.cg.shared.global [%0], [%1], 16, %2;"
                 :: "r"(dst), "l"(src), "r"(sz) : "memory");
}
#define CP_COMMIT() asm volatile("cp.async.commit_group;" ::: "memory")
#define CP_WAIT0()  asm volatile("cp.async.wait_group 0;" ::: "memory")
#define SWZ128(b) ((b) ^ (((b) >> 3) & 0x70))

__device__ __forceinline__ void split2h(float x, float y, uint32_t& hp, uint32_t& lp) {
    __half hx = __float2half_rn(x), hy = __float2half_rn(y);
    float lx = x - __half2float(hx), ly = y - __half2float(hy);
    hp = ((uint32_t)__half_as_ushort(hy) << 16) | __half_as_ushort(hx);
    lp = ((uint32_t)__half_as_ushort(__float2half_rn(ly)) << 16)
       | __half_as_ushort(__float2half_rn(lx));
}
__device__ __forceinline__ uint32_t pack_h(float x, float y) {
    return ((uint32_t)__half_as_ushort(__float2half_rn(y)) << 16)
         | __half_as_ushort(__float2half_rn(x));
}

// ================= smem layout: 64-row tiles, double-buffered =================
#define SM_BIAS 0        // 112 floats
#define SM_NRM  512      // 64 x 2 floats
#define SM_AH   1024     // 64 x 128B = 8192
#define SM_AL   (SM_AH + 8192)
#define SM_BH   (SM_AL + 8192)   // 112 x 128B = 14336
#define STG     30720
#define SM_TOTAL (1024 + 2 * STG)   // 62464 -> 3 CTAs/SM

// ================= combined prep: weights + nodes_feat split ==================
__global__ void prep_all(const float* __restrict__ W_emb, int Kemb, int KPe,
                         const float* __restrict__ pool_W,
                         const float* __restrict__ app_W, int n_layers, int w_total,
                         const float* __restrict__ X, int in_dim,
                         uint32_t* __restrict__ xh, uint32_t* __restrict__ xl,
                         int x_total) {
    int gid = blockIdx.x * blockDim.x + threadIdx.x;
    if (gid < w_total) {
        int idx = gid;
        const float* Wp = 0;
        int K = 0, KP = 0, rel = idx, off = 0, is_app = 0;
        int sz = 112 * (KPe >> 1);
        if (idx < sz) { Wp = W_emb; K = Kemb; KP = KPe; rel = idx; }
        else {
            off = sz;
            for (int l = 0; l < n_layers && !Wp; l++) {
                if (idx < off + 112 * 64) { Wp = pool_W + l * HH * HH; K = HH; KP = 128; rel = idx - off; }
                off += 112 * 64;
            }
            for (int l = 0; l < n_layers && !Wp; l++) {
                if (idx < off + 112 * 128) { Wp = app_W + l * 2 * HH * HH; K = 2 * HH; KP = 256; rel = idx - off; is_app = 1; }
                off += 112 * 128;
            }
            if (!Wp) return;
        }
        int nn = rel / (KP >> 1);
        int kp = rel - nn * (KP >> 1);
        float w[2];
#pragma unroll
        for (int q = 0; q < 2; q++) {
            int k = kp * 2 + q;
            int kk, valid;
            if (is_app) {
                if (k < 128) { kk = k; valid = (k < HH); }
                else { kk = HH + (k - 128); valid = (k - 128 < HH); }
            } else { kk = k; valid = (k < K); }
            w[q] = (nn < HH && valid) ? Wp[kk * HH + nn] : 0.f;
        }
        g_wh[idx] = pack_h(w[0], w[1]);
    } else {
        int idx = gid - w_total;
        if (idx >= x_total) return;
        int pu = KPe >> 1;
        int row = idx / pu;
        int kp = idx - row * pu;
        int k0 = kp * 2;
        float x0 = (k0 < in_dim) ? X[(size_t)row * in_dim + k0] : 0.f;
        float x1 = (k0 + 1 < in_dim) ? X[(size_t)row * in_dim + k0 + 1] : 0.f;
        uint32_t hp, lp;
        split2h(x0, x1, hp, lp);
        xh[idx] = hp;
        xl[idx] = lp;
    }
}

// ================= CSR build =================
__global__ void zero_deg_kernel(int n) {
    int i = blockIdx.x * blockDim.x + threadIdx.x;
    if (i < n) g_deg[i] = 0;
}
__global__ void hist_kernel(const int* __restrict__ dst, int e) {
    int i = blockIdx.x * blockDim.x + threadIdx.x;
    if (i < e) atomicAdd(&g_deg[dst[i]], 1);
}
__global__ void scan1_kernel(int n) {
    __shared__ int sh[SC_T];
    int t = threadIdx.x, b = blockIdx.x;
    int base = b * SC_CH + t * SC_I;
    int v[SC_I];
    int run = 0;
#pragma unroll
    for (int j = 0; j < SC_I; j++) {
        int idx = base + j;
        int x = (idx < n) ? g_deg[idx] : 0;
        run += x;
        v[j] = run;
    }
    sh[t] = run;
    __syncthreads();
    for (int off = 1; off < SC_T; off <<= 1) {
        int x = (t >= off) ? sh[t - off] : 0;
        __syncthreads();
        sh[t] += x;
        __syncthreads();
    }
    int excl = sh[t] - run;
#pragma unroll
    for (int j = 0; j < SC_I; j++) {
        int idx = base + j;
        if (idx < n) g_rowptr[1 + idx] = excl + v[j];
    }
    if (t == SC_T - 1) g_part[b] = sh[t];
}
__global__ void scan2_kernel(int nb) {
    __shared__ int sh[256];
    int t = threadIdx.x;
    int v = (t < nb) ? g_part[t] : 0;
    sh[t] = v;
    __syncthreads();
    for (int off = 1; off < 256; off <<= 1) {
        int x = (t >= off) ? sh[t - off] : 0;
        __syncthreads();
        sh[t] += x;
        __syncthreads();
    }
    if (t < nb) g_part[t] = sh[t] - v;
}
__global__ void scan3_kernel(int n) {
    int idx = blockIdx.x * blockDim.x + threadIdx.x;
    if (idx < n) {
        int val = g_rowptr[1 + idx] + g_part[idx / SC_CH];
        g_rowptr[1 + idx] = val;
        if (idx + 1 < n) g_cursor[idx + 1] = val;
    }
    if (idx == 0) { g_rowptr[0] = 0; g_cursor[0] = 0; }
}
__global__ void fillcsr_kernel(const int* __restrict__ src, const int* __restrict__ dst, int e) {
    int i = blockIdx.x * blockDim.x + threadIdx.x;
    if (i < e) {
        int d = dst[i];
        int pos = atomicAdd(&g_cursor[d], 1);
        g_col[pos] = src[i];
    }
}

// ================= persistent tensor-core GEMM (split-fp16) ===================
// terms: 2 = Ah@Bh + Al@Bh everywhere; 1 = Ah@Bh only;
//        3 = 2-term for chunks < NC1 (h part), 1-term for chunks >= NC1 (c part)
__global__ __launch_bounds__(256, 3)
void gemm_tc(const uint32_t* __restrict__ Ah1, const uint32_t* __restrict__ Al1,
             const uint32_t* __restrict__ Ah2, const uint32_t* __restrict__ Al2,
             int NC1, int apitch,
             const uint32_t* __restrict__ Wh, int wstride,
             const float* __restrict__ bias,
             float* __restrict__ out,
             const uint32_t* __restrict__ resH, const uint32_t* __restrict__ resL,
             uint32_t* __restrict__ outH, uint32_t* __restrict__ outL,
             int n, int K, int mode, int terms) {
    extern __shared__ char sm[];
    const uint32_t sb = smem_to_u32(sm);
    const int tid = threadIdx.x;
    const int wid = tid >> 5;
    const int lane = tid & 31;
    float* bias_s = (float*)(sm + SM_BIAS);
    float* nrm_s  = (float*)(sm + SM_NRM);

    if (tid < 112) bias_s[tid] = (tid < HH) ? bias[tid] : 0.f;

    const int rg = wid & 3;
    const int colh = wid >> 2;
    const int warp_r0 = rg * 16;
    const int a_row = warp_r0 + (lane & 15);
    const int a_kb  = (lane >> 4) * 16;
    const int b_row = lane & 7;
    const int b_kb  = ((lane >> 3) & 1) * 16;
    const int NC = K >> 6;
    const int tiles = (n + 63) >> 6;

    auto issue_fill = [&](int row0, int c, int s) {
        const uint32_t* srcH = (c < NC1) ? Ah1 : Ah2;
        const uint32_t* srcL = (c < NC1) ? Al1 : Al2;
        int coff = ((c < NC1) ? c : (c - NC1)) * 32;
        int two = (terms == 2) || (terms == 3 && c < NC1);
        int afill = two ? 1024 : 512;
        uint32_t base = sb + s * STG;
        for (int idx = tid; idx < afill; idx += 256) {
            int u = idx & 7;
            int row = (idx >> 3) & 63;
            int hi = idx < 512;
            int grow = row0 + row;
            const uint32_t* src = (hi ? srcH : srcL) + (size_t)grow * apitch + coff + u * 4;
            uint32_t dst = base + (hi ? SM_AH : SM_AL) + SWZ128((uint32_t)(row * 128 + u * 16));
            cp16(dst, src, grow < n ? 16 : 0);
        }
        int kc32 = c * 32;
        for (int idx = tid; idx < 896; idx += 256) {
            int u = idx & 7;
            int nn = idx >> 3;
            const uint32_t* src = Wh + nn * wstride + kc32 + u * 4;
            uint32_t dst = base + SM_BH + SWZ128((uint32_t)(nn * 128 + u * 16));
            cp16(dst, src, 16);
        }
    };

    int t = (int)blockIdx.x;
    if (t >= tiles) return;
    int s = 0;
    issue_fill(t * 64, 0, 0);
    CP_COMMIT();

    for (; t < tiles; t += (int)gridDim.x) {
        const int row0 = t * 64;
        float acc[7][4];
#pragma unroll
        for (int nt = 0; nt < 7; nt++)
#pragma unroll
            for (int q = 0; q < 4; q++) acc[nt][q] = 0.f;

        for (int c = 0; c < NC; c++) {
            CP_WAIT0();
            __syncthreads();
            int ntile = (c + 1 < NC) ? t : t + (int)gridDim.x;
            int nch   = (c + 1 < NC) ? c + 1 : 0;
            if (ntile < tiles) {
                issue_fill(ntile * 64, nch, s ^ 1);
                CP_COMMIT();
            }
            uint32_t base = sb + s * STG;
            const int two = (terms == 2) || (terms == 3 && c < NC1);
#pragma unroll
            for (int ks = 0; ks < 4; ks++) {
                uint32_t aloc = SWZ128((uint32_t)(a_row * 128 + a_kb + ks * 32));
                uint32_t ah[4], al[4];
                ldm_x4(ah, base + SM_AH + aloc);
                if (two) ldm_x4(al, base + SM_AL + aloc);
                uint32_t bloc = SWZ128((uint32_t)(b_row * 128 + b_kb + ks * 32));
                uint32_t bh[7][2];
#pragma unroll
                for (int nt = 0; nt < 7; nt++)
                    ldm_x2(bh[nt], base + SM_BH + bloc + (colh * 7 + nt) * 1024);
#pragma unroll
                for (int nt = 0; nt < 7; nt++) {
                    mma_fp16(acc[nt], ah, bh[nt]);
                    if (two) mma_fp16(acc[nt], al, bh[nt]);
                }
            }
            s ^= 1;
        }

        // ---- epilogue ----
        const int erl = warp_r0 + (lane >> 2);
        const int ec = (lane & 3) * 2;
        const int glo = row0 + erl, ghi = glo + 8;
        float ss0 = 0.f, ss1 = 0.f;
#pragma unroll
        for (int nt = 0; nt < 7; nt++) {
            int col = (colh * 7 + nt) * 8 + ec;
            float b0 = bias_s[col], b1 = bias_s[col + 1];
            acc[nt][0] += b0; acc[nt][1] += b1;
            acc[nt][2] += b0; acc[nt][3] += b1;
            if (mode == 2) {
                ss0 += acc[nt][0] * acc[nt][0] + acc[nt][1] * acc[nt][1];
                ss1 += acc[nt][2] * acc[nt][2] + acc[nt][3] * acc[nt][3];
            }
        }
        float s0 = 1.f, s1 = 1.f;
        if (mode == 2) {
            ss0 += __shfl_xor_sync(0xFFFFFFFFu, ss0, 1);
            ss0 += __shfl_xor_sync(0xFFFFFFFFu, ss0, 2);
            ss1 += __shfl_xor_sync(0xFFFFFFFFu, ss1, 1);
            ss1 += __shfl_xor_sync(0xFFFFFFFFu, ss1, 2);
            if ((lane & 3) == 0) {
                nrm_s[erl * 2 + colh] = ss0;
                nrm_s[(erl + 8) * 2 + colh] = ss1;
            }
            __syncthreads();
            s0 = 1.f / fmaxf(sqrtf(nrm_s[erl * 2] + nrm_s[erl * 2 + 1]), 1e-12f);
            s1 = 1.f / fmaxf(sqrtf(nrm_s[(erl + 8) * 2] + nrm_s[(erl + 8) * 2 + 1]), 1e-12f);
            __syncthreads();
        }
#pragma unroll
        for (int nt = 0; nt < 7; nt++) {
            int col = (colh * 7 + nt) * 8 + ec;
            if (col >= HH) continue;
            float v0 = acc[nt][0], v1 = acc[nt][1], v2 = acc[nt][2], v3 = acc[nt][3];
            if (mode == 3) {
                v0 = fmaxf(v0, 0.f); v1 = fmaxf(v1, 0.f);
                v2 = fmaxf(v2, 0.f); v3 = fmaxf(v3, 0.f);
                uint32_t* zo = (uint32_t*)out;
                if (glo < n) zo[(size_t)glo * ZP + (col >> 1)] = pack_h(v0, v1);
                if (ghi < n) zo[(size_t)ghi * ZP + (col >> 1)] = pack_h(v2, v3);
                continue;
            }
            if (mode == 2) {
                if (glo < n) {
                    uint32_t hp = resH[(size_t)glo * HP + (col >> 1)];
                    uint32_t lp = resL[(size_t)glo * HP + (col >> 1)];
                    float2 fh = __half22float2(*(__half2*)&hp);
                    float2 fl = __half22float2(*(__half2*)&lp);
                    v0 = (fh.x + fl.x) + fmaxf(v0 * s0, 0.f);
                    v1 = (fh.y + fl.y) + fmaxf(v1 * s0, 0.f);
                }
                if (ghi < n) {
                    uint32_t hp = resH[(size_t)ghi * HP + (col >> 1)];
                    uint32_t lp = resL[(size_t)ghi * HP + (col >> 1)];
                    float2 fh = __half22float2(*(__half2*)&hp);
                    float2 fl = __half22float2(*(__half2*)&lp);
                    v2 = (fh.x + fl.x) + fmaxf(v2 * s1, 0.f);
                    v3 = (fh.y + fl.y) + fmaxf(v3 * s1, 0.f);
                }
            }
            if (out) {
                if (glo < n) *(float2*)(out + (size_t)glo * HH + col) = make_float2(v0, v1);
                if (ghi < n) *(float2*)(out + (size_t)ghi * HH + col) = make_float2(v2, v3);
            }
            if (outH) {
                uint32_t hp, lp;
                if (glo < n) {
                    split2h(v0, v1, hp, lp);
                    outH[(size_t)glo * HP + (col >> 1)] = hp;
                    outL[(size_t)glo * HP + (col >> 1)] = lp;
                }
                if (ghi < n) {
                    split2h(v2, v3, hp, lp);
                    outH[(size_t)ghi * HP + (col >> 1)] = hp;
                    outL[(size_t)ghi * HP + (col >> 1)] = lp;
                }
            }
        }
    }
}

// ===== mean aggregation over CSR: z packed fp16 (pitch ZP) -> c hi fp16 (pitch HP)
__global__ void aggregate_kernel(const uint32_t* __restrict__ zp,
                                 uint32_t* __restrict__ ch, int n) {
    int w = (blockIdx.x * blockDim.x + threadIdx.x) >> 5;
    int lane = threadIdx.x & 31;
    if (w >= n || lane >= 27) return;
    int s = g_rowptr[w], e = g_rowptr[w + 1];
    float a0 = 0.f, a1 = 0.f, a2 = 0.f, a3 = 0.f;
    int i = s;
    for (; i + 7 < e; i += 8) {
        int cc[8];
#pragma unroll
        for (int q = 0; q < 8; q++) cc[q] = g_col[i + q];
        uint2 u[8];
#pragma unroll
        for (int q = 0; q < 8; q++) u[q] = ((const uint2*)(zp + (size_t)cc[q] * ZP))[lane];
#pragma unroll
        for (int q = 0; q < 8; q++) {
            float2 f0 = __half22float2(*(__half2*)&u[q].x);
            float2 f1 = __half22float2(*(__half2*)&u[q].y);
            a0 += f0.x; a1 += f0.y; a2 += f1.x; a3 += f1.y;
        }
    }
    if (i + 3 < e) {
        int cc[4];
#pragma unroll
        for (int q = 0; q < 4; q++) cc[q] = g_col[i + q];
        uint2 u[4];
#pragma unroll
        for (int q = 0; q < 4; q++) u[q] = ((const uint2*)(zp + (size_t)cc[q] * ZP))[lane];
#pragma unroll
        for (int q = 0; q < 4; q++) {
            float2 f0 = __half22float2(*(__half2*)&u[q].x);
            float2 f1 = __half22float2(*(__half2*)&u[q].y);
            a0 += f0.x; a1 += f0.y; a2 += f1.x; a3 += f1.y;
        }
        i += 4;
    }
    for (; i < e; i++) {
        uint2 u0 = ((const uint2*)(zp + (size_t)g_col[i] * ZP))[lane];
        float2 f0 = __half22float2(*(__half2*)&u0.x);
        float2 f1 = __half22float2(*(__half2*)&u0.y);
        a0 += f0.x; a1 += f0.y; a2 += f1.x; a3 += f1.y;
    }
    float inv = 1.f / (float)max(e - s, 1);
    ch[(size_t)w * HP + lane * 2]     = pack_h(a0 * inv, a1 * inv);
    ch[(size_t)w * HP + lane * 2 + 1] = pack_h(a2 * inv, a3 * inv);
}

// ================= graph readout: block per graph (gids SORTED) ===============
__global__ void readout_graph(const float* __restrict__ h, const int* __restrict__ gids,
                              float* __restrict__ out, int n) {
    __shared__ float part[8][112];
    const int g = blockIdx.x;
    const int tid = threadIdx.x;
    const int wid = tid >> 5;
    const int lane = tid & 31;
    int lo = 0, hi = n;
    while (lo < hi) { int m = (lo + hi) >> 1; if (gids[m] < g) lo = m + 1; else hi = m; }
    const int start = lo;
    hi = n;
    while (lo < hi) { int m = (lo + hi) >> 1; if (gids[m] < g + 1) lo = m + 1; else hi = m; }
    const int end = lo;

    float a0 = 0.f, a1 = 0.f, a2 = 0.f, a3 = 0.f;
    if (lane < 27) {
        for (int r = start + wid; r < end; r += 8) {
            float4 v = ((const float4*)(h + (size_t)r * HH))[lane];
            a0 += v.x; a1 += v.y; a2 += v.z; a3 += v.w;
        }
        part[wid][lane * 4]     = a0;
        part[wid][lane * 4 + 1] = a1;
        part[wid][lane * 4 + 2] = a2;
        part[wid][lane * 4 + 3] = a3;
    }
    __syncthreads();
    if (tid < HH) {
        float sum = 0.f;
#pragma unroll
        for (int wq = 0; wq < 8; wq++) sum += part[wq][tid];
        out[(size_t)g * HH + tid] = sum / fmaxf((float)(end - start), 1.f);
    }
}

// ================= launch =================
extern "C" void kernel_launch(void* const* d_in, const int* in_sizes, int n_in,
                              void* d_out, int out_size) {
    const float* nodes_feat = (const float*)d_in[0];
    const float* W_emb  = (const float*)d_in[4];
    const float* b_emb  = (const float*)d_in[5];
    const float* pool_W = (const float*)d_in[6];
    const float* pool_b = (const float*)d_in[7];
    const float* app_W  = (const float*)d_in[8];
    const float* app_b  = (const float*)d_in[9];
    const int* src  = (const int*)d_in[10];
    const int* dst  = (const int*)d_in[11];
    const int* gids = (const int*)d_in[12];

    const int n = in_sizes[12];
    const int e = in_sizes[10];
    const int in_dim = in_sizes[4] / HH;
    const int n_layers = in_sizes[6] / (HH * HH);
    const int G = out_size / HH;

    float *hP, *zP;
    uint32_t *hhP, *hlP, *chP, *clP, *whP;
    cudaGetSymbolAddress((void**)&hP, g_h);
    cudaGetSymbolAddress((void**)&zP, g_z);
    cudaGetSymbolAddress((void**)&hhP, g_hh);
    cudaGetSymbolAddress((void**)&hlP, g_hl);
    cudaGetSymbolAddress((void**)&chP, g_ch);
    cudaGetSymbolAddress((void**)&clP, g_cl);
    cudaGetSymbolAddress((void**)&whP, g_wh);

    cudaFuncSetAttribute(gemm_tc, cudaFuncAttributeMaxDynamicSharedMemorySize, SM_TOTAL);

    static cudaStream_t s2 = 0;
    static cudaEvent_t evFork = 0, evJoin = 0;
    if (!s2) {
        cudaStreamCreateWithFlags(&s2, cudaStreamNonBlocking);
        cudaEventCreateWithFlags(&evFork, cudaEventDisableTiming);
        cudaEventCreateWithFlags(&evJoin, cudaEventDisableTiming);
    }

    const int KPe = ((in_dim + 63) / 64) * 64;
    const int u_emb = 112 * (KPe >> 1);
    const int u_pool = 112 * 64;
    const int u_app = 112 * 128;
    const int w_total = u_emb + n_layers * (u_pool + u_app);
    const int x_total = n * (KPe >> 1);

    const int tiles = (n + 63) / 64;
    const int pg = tiles < PGRID ? tiles : PGRID;
    int warp_blocks = ((n * 32) + 255) / 256;

    // ---- fork: CSR build on side stream (depends only on src/dst) ----
    cudaEventRecord(evFork, 0);
    cudaStreamWaitEvent(s2, evFork, 0);
    zero_deg_kernel<<<(n + 255) / 256, 256, 0, s2>>>(n);
    hist_kernel<<<(e + 255) / 256, 256, 0, s2>>>(dst, e);
    int nb = (n + SC_CH - 1) / SC_CH;
    scan1_kernel<<<nb, SC_T, 0, s2>>>(n);
    scan2_kernel<<<1, 256, 0, s2>>>(nb);
    scan3_kernel<<<(n + 255) / 256, 256, 0, s2>>>(n);
    fillcsr_kernel<<<(e + 255) / 256, 256, 0, s2>>>(src, dst, e);
    cudaEventRecord(evJoin, s2);

    // ---- main stream: combined prep + embedding ----
    prep_all<<<(w_total + x_total + 255) / 256, 256>>>(
        W_emb, in_dim, KPe, pool_W, app_W, n_layers, w_total,
        nodes_feat, in_dim, chP, clP, x_total);
    gemm_tc<<<pg, 256, SM_TOTAL>>>(chP, clP, (const uint32_t*)0, (const uint32_t*)0,
                                   KPe >> 6, KPe >> 1,
                                   whP, KPe >> 1,
                                   b_emb, (float*)0, (const uint32_t*)0, (const uint32_t*)0,
                                   hhP, hlP,
                                   n, KPe, 0, 2);

    bool joined = false;
    for (int l = 0; l < n_layers; l++) {
        const float* pb = pool_b + (size_t)l * HH;
        const float* ab = app_b + (size_t)l * HH;
        const uint32_t* pWh = whP + u_emb + l * u_pool;
        const uint32_t* aWh = whP + u_emb + n_layers * u_pool + l * u_app;

        // z = relu(h @ pool_W + pool_b) -> packed fp16; single-term
        gemm_tc<<<pg, 256, SM_TOTAL>>>(hhP, hlP, (const uint32_t*)0, (const uint32_t*)0,
                                       2, HP,
                                       pWh, 64,
                                       pb, zP, (const uint32_t*)0, (const uint32_t*)0,
                                       (uint32_t*)0, (uint32_t*)0,
                                       n, 128, 3, 1);
        if (!joined) { cudaStreamWaitEvent(0, evJoin, 0); joined = true; }
        // c = mean_{u in N(v)} z[u] -> hi fp16 only
        aggregate_kernel<<<warp_blocks, 256>>>((const uint32_t*)zP, chP, n);
        // h = h + relu(l2norm([h|c] @ app_W + app_b)); 2-term on h, 1-term on c
        int last = (l == n_layers - 1);
        gemm_tc<<<pg, 256, SM_TOTAL>>>(hhP, hlP, chP, (const uint32_t*)0,
                                       2, HP,
                                       aWh, 128,
                                       ab,
                                       last ? hP : (float*)0,
                                       hhP, hlP,
                                       last ? (uint32_t*)0 : hhP,
                                       last ? (uint32_t*)0 : hlP,
                                       n, 256, 2, 3);
    }

    // ---- readout: one block per graph, no atomics (gids sorted) ----
    readout_graph<<<G, 256>>>(hP, gids, (float*)d_out, n);
}

// round 17
// speedup vs baseline: 1.0845x; 1.0512x over previous
#include <cuda_runtime.h>
#include <cuda_fp16.h>
#include <math.h>
#include <stdint.h>

#define HH 108
#define HP 64               // padded u32 pitch for split rows (256B)
#define ZP 54               // u32 pitch for packed fp16 z rows
#define NCAP 100000
#define ECAP 1600000
#define GCAP 1024
#define SC_T 256
#define SC_I 8
#define SC_CH (SC_T * SC_I)
#define PGRID 444           // persistent grid: 148 SM x 3 CTAs

// -------- device scratch --------
__device__ float    g_h[NCAP * HH];
__device__ float    g_z[NCAP * HH];    // packed fp16 z (u32, pitch ZP)
__device__ uint32_t g_hh[NCAP * HP];
__device__ uint32_t g_hl[NCAP * HP];
__device__ uint32_t g_ch[NCAP * HP];   // also scratch for split nodes_feat before layer 0
__device__ uint32_t g_cl[NCAP * HP];   // split nodes_feat lo
__device__ uint32_t g_wh[65536];
__device__ int   g_deg[NCAP];
__device__ int   g_rowptr[NCAP + 1];
__device__ int   g_cursor[NCAP];
__device__ int   g_col[ECAP];
__device__ int   g_part[256];

// ================= helpers =================
__device__ __forceinline__ uint32_t smem_to_u32(const void* smem_ptr) {
    uint32_t addr;
    asm("{ .reg .u64 tmp; cvta.to.shared.u64 tmp, %1; cvt.u32.u64 %0, tmp; }"
        : "=r"(addr) : "l"(smem_ptr));
    return addr;
}
__device__ __forceinline__ void ldm_x4(uint32_t* r, uint32_t addr) {
    asm volatile("ldmatrix.sync.aligned.m8n8.x4.shared.b16 {%0,%1,%2,%3}, [%4];"
        : "=r"(r[0]), "=r"(r[1]), "=r"(r[2]), "=r"(r[3]) : "r"(addr));
}
__device__ __forceinline__ void ldm_x2(uint32_t* r, uint32_t addr) {
    asm volatile("ldmatrix.sync.aligned.m8n8.x2.shared.b16 {%0,%1}, [%2];"
        : "=r"(r[0]), "=r"(r[1]) : "r"(addr));
}
__device__ __forceinline__ void mma_fp16(float* c, const uint32_t* a, const uint32_t* b) {
    asm volatile(
        "mma.sync.aligned.m16n8k16.row.col.f32.f16.f16.f32 "
        "{%0,%1,%2,%3}, {%4,%5,%6,%7}, {%8,%9}, {%0,%1,%2,%3};"
        : "+f"(c[0]), "+f"(c[1]), "+f"(c[2]), "+f"(c[3])
        : "r"(a[0]), "r"(a[1]), "r"(a[2]), "r"(a[3]), "r"(b[0]), "r"(b[1]));
}
__device__ __forceinline__ void cp16(uint32_t dst, const void* src, int sz) {
    asm volatile("cp.async.cg.shared.global [%0], [%1], 16, %2;"
                 :: "r"(dst), "l"(src), "r"(sz) : "memory");
}
#define CP_COMMIT() asm volatile("cp.async.commit_group;" ::: "memory")
#define CP_WAIT0()  asm volatile("cp.async.wait_group 0;" ::: "memory")
#define SWZ128(b) ((b) ^ (((b) >> 3) & 0x70))

__device__ __forceinline__ void split2h(float x, float y, uint32_t& hp, uint32_t& lp) {
    __half hx = __float2half_rn(x), hy = __float2half_rn(y);
    float lx = x - __half2float(hx), ly = y - __half2float(hy);
    hp = ((uint32_t)__half_as_ushort(hy) << 16) | __half_as_ushort(hx);
    lp = ((uint32_t)__half_as_ushort(__float2half_rn(ly)) << 16)
       | __half_as_ushort(__float2half_rn(lx));
}
__device__ __forceinline__ uint32_t pack_h(float x, float y) {
    return ((uint32_t)__half_as_ushort(__float2half_rn(y)) << 16)
         | __half_as_ushort(__float2half_rn(x));
}

// ================= smem layout: 64-row tiles, double-buffered =================
#define SM_BIAS 0        // 112 floats
#define SM_NRM  512      // 64 x 2 floats
#define SM_AH   1024     // 64 x 128B = 8192
#define SM_AL   (SM_AH + 8192)
#define SM_BH   (SM_AL + 8192)   // 112 x 128B = 14336
#define STG     30720
#define SM_TOTAL (1024 + 2 * STG)   // 62464 -> 3 CTAs/SM

// ================= combined prep: weights + nodes_feat split ==================
__global__ void prep_all(const float* __restrict__ W_emb, int Kemb, int KPe,
                         const float* __restrict__ pool_W,
                         const float* __restrict__ app_W, int n_layers, int w_total,
                         const float* __restrict__ X, int in_dim,
                         uint32_t* __restrict__ xh, uint32_t* __restrict__ xl,
                         int x_total) {
    int gid = blockIdx.x * blockDim.x + threadIdx.x;
    if (gid < w_total) {
        int idx = gid;
        const float* Wp = 0;
        int K = 0, KP = 0, rel = idx, off = 0, is_app = 0;
        int sz = 112 * (KPe >> 1);
        if (idx < sz) { Wp = W_emb; K = Kemb; KP = KPe; rel = idx; }
        else {
            off = sz;
            for (int l = 0; l < n_layers && !Wp; l++) {
                if (idx < off + 112 * 64) { Wp = pool_W + l * HH * HH; K = HH; KP = 128; rel = idx - off; }
                off += 112 * 64;
            }
            for (int l = 0; l < n_layers && !Wp; l++) {
                if (idx < off + 112 * 128) { Wp = app_W + l * 2 * HH * HH; K = 2 * HH; KP = 256; rel = idx - off; is_app = 1; }
                off += 112 * 128;
            }
            if (!Wp) return;
        }
        int nn = rel / (KP >> 1);
        int kp = rel - nn * (KP >> 1);
        float w[2];
#pragma unroll
        for (int q = 0; q < 2; q++) {
            int k = kp * 2 + q;
            int kk, valid;
            if (is_app) {
                if (k < 128) { kk = k; valid = (k < HH); }
                else { kk = HH + (k - 128); valid = (k - 128 < HH); }
            } else { kk = k; valid = (k < K); }
            w[q] = (nn < HH && valid) ? Wp[kk * HH + nn] : 0.f;
        }
        g_wh[idx] = pack_h(w[0], w[1]);
    } else {
        int idx = gid - w_total;
        if (idx >= x_total) return;
        int pu = KPe >> 1;
        int row = idx / pu;
        int kp = idx - row * pu;
        int k0 = kp * 2;
        float x0 = (k0 < in_dim) ? X[(size_t)row * in_dim + k0] : 0.f;
        float x1 = (k0 + 1 < in_dim) ? X[(size_t)row * in_dim + k0 + 1] : 0.f;
        uint32_t hp, lp;
        split2h(x0, x1, hp, lp);
        xh[idx] = hp;
        xl[idx] = lp;
    }
}

// ================= CSR build =================
__global__ void zero_deg_kernel(int n) {
    int i = blockIdx.x * blockDim.x + threadIdx.x;
    if (i < n) g_deg[i] = 0;
}
__global__ void hist_kernel(const int* __restrict__ dst, int e) {
    int i = blockIdx.x * blockDim.x + threadIdx.x;
    if (i < e) atomicAdd(&g_deg[dst[i]], 1);
}
__global__ void scan1_kernel(int n) {
    __shared__ int sh[SC_T];
    int t = threadIdx.x, b = blockIdx.x;
    int base = b * SC_CH + t * SC_I;
    int v[SC_I];
    int run = 0;
#pragma unroll
    for (int j = 0; j < SC_I; j++) {
        int idx = base + j;
        int x = (idx < n) ? g_deg[idx] : 0;
        run += x;
        v[j] = run;
    }
    sh[t] = run;
    __syncthreads();
    for (int off = 1; off < SC_T; off <<= 1) {
        int x = (t >= off) ? sh[t - off] : 0;
        __syncthreads();
        sh[t] += x;
        __syncthreads();
    }
    int excl = sh[t] - run;
#pragma unroll
    for (int j = 0; j < SC_I; j++) {
        int idx = base + j;
        if (idx < n) g_rowptr[1 + idx] = excl + v[j];
    }
    if (t == SC_T - 1) g_part[b] = sh[t];
}
__global__ void scan2_kernel(int nb) {
    __shared__ int sh[256];
    int t = threadIdx.x;
    int v = (t < nb) ? g_part[t] : 0;
    sh[t] = v;
    __syncthreads();
    for (int off = 1; off < 256; off <<= 1) {
        int x = (t >= off) ? sh[t - off] : 0;
        __syncthreads();
        sh[t] += x;
        __syncthreads();
    }
    if (t < nb) g_part[t] = sh[t] - v;
}
__global__ void scan3_kernel(int n) {
    int idx = blockIdx.x * blockDim.x + threadIdx.x;
    if (idx < n) {
        int val = g_rowptr[1 + idx] + g_part[idx / SC_CH];
        g_rowptr[1 + idx] = val;
        if (idx + 1 < n) g_cursor[idx + 1] = val;
    }
    if (idx == 0) { g_rowptr[0] = 0; g_cursor[0] = 0; }
}
__global__ void fillcsr_kernel(const int* __restrict__ src, const int* __restrict__ dst, int e) {
    int i = blockIdx.x * blockDim.x + threadIdx.x;
    if (i < e) {
        int d = dst[i];
        int pos = atomicAdd(&g_cursor[d], 1);
        g_col[pos] = src[i];
    }
}

// ================= persistent tensor-core GEMM (split-fp16) ===================
// terms: 2 = Ah@Bh + Al@Bh everywhere; 3 = 2-term chunks < NC1, 1-term >= NC1
// If Wp2 != 0: fused pool — after the epilogue for each tile, compute
// z = relu(newh @ Wp2 + pbias2) from the register-resident newh (1-term fp16),
// reusing the just-freed pipeline stage. Numerically identical to the old
// standalone pool (it consumed the hi-split of h, which pack_h(newh) equals).
__global__ __launch_bounds__(256, 3)
void gemm_tc(const uint32_t* __restrict__ Ah1, const uint32_t* __restrict__ Al1,
             const uint32_t* __restrict__ Ah2, const uint32_t* __restrict__ Al2,
             int NC1, int apitch,
             const uint32_t* __restrict__ Wh, int wstride,
             const float* __restrict__ bias,
             float* __restrict__ out,
             const uint32_t* __restrict__ resH, const uint32_t* __restrict__ resL,
             uint32_t* __restrict__ outH, uint32_t* __restrict__ outL,
             int n, int K, int mode, int terms,
             const uint32_t* __restrict__ Wp2, const float* __restrict__ pbias2,
             uint32_t* __restrict__ zout) {
    extern __shared__ char sm[];
    const uint32_t sb = smem_to_u32(sm);
    const int tid = threadIdx.x;
    const int wid = tid >> 5;
    const int lane = tid & 31;
    float* bias_s = (float*)(sm + SM_BIAS);
    float* nrm_s  = (float*)(sm + SM_NRM);

    if (tid < 112) bias_s[tid] = (tid < HH) ? bias[tid] : 0.f;

    const int rg = wid & 3;
    const int colh = wid >> 2;
    const int warp_r0 = rg * 16;
    const int a_row = warp_r0 + (lane & 15);
    const int a_kb  = (lane >> 4) * 16;
    const int b_row = lane & 7;
    const int b_kb  = ((lane >> 3) & 1) * 16;
    const int NC = K >> 6;
    const int tiles = (n + 63) >> 6;

    auto issue_fill = [&](int row0, int c, int s) {
        const uint32_t* srcH = (c < NC1) ? Ah1 : Ah2;
        const uint32_t* srcL = (c < NC1) ? Al1 : Al2;
        int coff = ((c < NC1) ? c : (c - NC1)) * 32;
        int two = (terms == 2) || (terms == 3 && c < NC1);
        int afill = two ? 1024 : 512;
        uint32_t base = sb + s * STG;
        for (int idx = tid; idx < afill; idx += 256) {
            int u = idx & 7;
            int row = (idx >> 3) & 63;
            int hi = idx < 512;
            int grow = row0 + row;
            const uint32_t* src = (hi ? srcH : srcL) + (size_t)grow * apitch + coff + u * 4;
            uint32_t dst = base + (hi ? SM_AH : SM_AL) + SWZ128((uint32_t)(row * 128 + u * 16));
            cp16(dst, src, grow < n ? 16 : 0);
        }
        int kc32 = c * 32;
        for (int idx = tid; idx < 896; idx += 256) {
            int u = idx & 7;
            int nn = idx >> 3;
            const uint32_t* src = Wh + nn * wstride + kc32 + u * 4;
            uint32_t dst = base + SM_BH + SWZ128((uint32_t)(nn * 128 + u * 16));
            cp16(dst, src, 16);
        }
    };

    int t = (int)blockIdx.x;
    if (t >= tiles) return;
    int s = 0;
    issue_fill(t * 64, 0, 0);
    CP_COMMIT();

    for (; t < tiles; t += (int)gridDim.x) {
        const int row0 = t * 64;
        float acc[7][4];
#pragma unroll
        for (int nt = 0; nt < 7; nt++)
#pragma unroll
            for (int q = 0; q < 4; q++) acc[nt][q] = 0.f;

        for (int c = 0; c < NC; c++) {
            CP_WAIT0();
            __syncthreads();
            int ntile = (c + 1 < NC) ? t : t + (int)gridDim.x;
            int nch   = (c + 1 < NC) ? c + 1 : 0;
            if (ntile < tiles) {
                issue_fill(ntile * 64, nch, s ^ 1);
                CP_COMMIT();
            }
            uint32_t base = sb + s * STG;
            const int two = (terms == 2) || (terms == 3 && c < NC1);
#pragma unroll
            for (int ks = 0; ks < 4; ks++) {
                uint32_t aloc = SWZ128((uint32_t)(a_row * 128 + a_kb + ks * 32));
                uint32_t ah[4], al[4];
                ldm_x4(ah, base + SM_AH + aloc);
                if (two) ldm_x4(al, base + SM_AL + aloc);
                uint32_t bloc = SWZ128((uint32_t)(b_row * 128 + b_kb + ks * 32));
                uint32_t bh[7][2];
#pragma unroll
                for (int nt = 0; nt < 7; nt++)
                    ldm_x2(bh[nt], base + SM_BH + bloc + (colh * 7 + nt) * 1024);
#pragma unroll
                for (int nt = 0; nt < 7; nt++) {
                    mma_fp16(acc[nt], ah, bh[nt]);
                    if (two) mma_fp16(acc[nt], al, bh[nt]);
                }
            }
            s ^= 1;
        }

        // ---- epilogue: bias / norm / residual; transform acc -> final h ----
        const int erl = warp_r0 + (lane >> 2);
        const int ec = (lane & 3) * 2;
        const int glo = row0 + erl, ghi = glo + 8;
        float ss0 = 0.f, ss1 = 0.f;
#pragma unroll
        for (int nt = 0; nt < 7; nt++) {
            int col = (colh * 7 + nt) * 8 + ec;
            float b0 = bias_s[col], b1 = bias_s[col + 1];
            acc[nt][0] += b0; acc[nt][1] += b1;
            acc[nt][2] += b0; acc[nt][3] += b1;
            if (mode == 2) {
                ss0 += acc[nt][0] * acc[nt][0] + acc[nt][1] * acc[nt][1];
                ss1 += acc[nt][2] * acc[nt][2] + acc[nt][3] * acc[nt][3];
            }
        }
        float s0 = 1.f, s1 = 1.f;
        if (mode == 2) {
            ss0 += __shfl_xor_sync(0xFFFFFFFFu, ss0, 1);
            ss0 += __shfl_xor_sync(0xFFFFFFFFu, ss0, 2);
            ss1 += __shfl_xor_sync(0xFFFFFFFFu, ss1, 1);
            ss1 += __shfl_xor_sync(0xFFFFFFFFu, ss1, 2);
            if ((lane & 3) == 0) {
                nrm_s[erl * 2 + colh] = ss0;
                nrm_s[(erl + 8) * 2 + colh] = ss1;
            }
            __syncthreads();
            s0 = 1.f / fmaxf(sqrtf(nrm_s[erl * 2] + nrm_s[erl * 2 + 1]), 1e-12f);
            s1 = 1.f / fmaxf(sqrtf(nrm_s[(erl + 8) * 2] + nrm_s[(erl + 8) * 2 + 1]), 1e-12f);
            __syncthreads();
        }
#pragma unroll
        for (int nt = 0; nt < 7; nt++) {
            int col = (colh * 7 + nt) * 8 + ec;
            float v0 = acc[nt][0], v1 = acc[nt][1], v2 = acc[nt][2], v3 = acc[nt][3];
            if (mode == 2) {
                if (glo < n) {
                    uint32_t hp = resH[(size_t)glo * HP + (col >> 1)];
                    uint32_t lp = resL[(size_t)glo * HP + (col >> 1)];
                    float2 fh = __half22float2(*(__half2*)&hp);
                    float2 fl = __half22float2(*(__half2*)&lp);
                    v0 = (fh.x + fl.x) + fmaxf(v0 * s0, 0.f);
                    v1 = (fh.y + fl.y) + fmaxf(v1 * s0, 0.f);
                }
                if (ghi < n) {
                    uint32_t hp = resH[(size_t)ghi * HP + (col >> 1)];
                    uint32_t lp = resL[(size_t)ghi * HP + (col >> 1)];
                    float2 fh = __half22float2(*(__half2*)&hp);
                    float2 fl = __half22float2(*(__half2*)&lp);
                    v2 = (fh.x + fl.x) + fmaxf(v2 * s1, 0.f);
                    v3 = (fh.y + fl.y) + fmaxf(v3 * s1, 0.f);
                }
            }
            acc[nt][0] = v0; acc[nt][1] = v1; acc[nt][2] = v2; acc[nt][3] = v3;
            if (col < HH) {
                if (out) {
                    if (glo < n) *(float2*)(out + (size_t)glo * HH + col) = make_float2(v0, v1);
                    if (ghi < n) *(float2*)(out + (size_t)ghi * HH + col) = make_float2(v2, v3);
                }
                if (outH) {
                    uint32_t hp, lp;
                    if (glo < n) {
                        split2h(v0, v1, hp, lp);
                        outH[(size_t)glo * HP + (col >> 1)] = hp;
                        outL[(size_t)glo * HP + (col >> 1)] = lp;
                    }
                    if (ghi < n) {
                        split2h(v2, v3, hp, lp);
                        outH[(size_t)ghi * HP + (col >> 1)] = hp;
                        outL[(size_t)ghi * HP + (col >> 1)] = lp;
                    }
                }
            }
        }

        // ---- fused pool: z = relu(newh @ Wp2 + pbias2), 1-term fp16 ----
        if (Wp2) {
            __syncthreads();  // all warps done reading stage ps
            const uint32_t pbase = sb + (s ^ 1) * STG;
            char* pc = sm + (size_t)(s ^ 1) * STG;
            // pool B chunk 0 (overlaps the staging below)
            for (int idx = tid; idx < 896; idx += 256) {
                int u = idx & 7, nn = idx >> 3;
                cp16(pbase + SM_BH + SWZ128((uint32_t)(nn * 128 + u * 16)),
                     Wp2 + nn * 64 + u * 4, 16);
            }
            CP_COMMIT();
            // stage newh (fp16 hi) as A tile: AH = k0..63, AL = k64..127 (pad 0)
#pragma unroll
            for (int nt = 0; nt < 7; nt++) {
                int col = (colh * 7 + nt) * 8 + ec;
                uint32_t plo = (col < HH) ? pack_h(acc[nt][0], acc[nt][1]) : 0u;
                uint32_t phi = (col < HH) ? pack_h(acc[nt][2], acc[nt][3]) : 0u;
                int reg = (col < 64) ? SM_AH : SM_AL;
                int cb = (col < 64) ? col * 2 : (col - 64) * 2;
                *(uint32_t*)(pc + reg + SWZ128((uint32_t)(erl * 128 + cb))) = plo;
                *(uint32_t*)(pc + reg + SWZ128((uint32_t)((erl + 8) * 128 + cb))) = phi;
            }
            for (int idx = tid; idx < 512; idx += 256) {   // zero pad k112..127
                int row = idx >> 3, u = idx & 7;
                *(uint32_t*)(pc + SM_AL + SWZ128((uint32_t)(row * 128 + 96 + u * 4))) = 0u;
            }
            CP_WAIT0();          // pool B c0 (and next-tile prefetch) landed
            __syncthreads();
            float acc2[7][4];
#pragma unroll
            for (int nt = 0; nt < 7; nt++)
#pragma unroll
                for (int q = 0; q < 4; q++) acc2[nt][q] = 0.f;
#pragma unroll
            for (int ks = 0; ks < 4; ks++) {   // chunk 0: k0..63
                uint32_t ah[4];
                ldm_x4(ah, pbase + SM_AH + SWZ128((uint32_t)(a_row * 128 + a_kb + ks * 32)));
                uint32_t bloc = SWZ128((uint32_t)(b_row * 128 + b_kb + ks * 32));
                uint32_t bh[7][2];
#pragma unroll
                for (int nt = 0; nt < 7; nt++)
                    ldm_x2(bh[nt], pbase + SM_BH + bloc + (colh * 7 + nt) * 1024);
#pragma unroll
                for (int nt = 0; nt < 7; nt++) mma_fp16(acc2[nt], ah, bh[nt]);
            }
            __syncthreads();
            for (int idx = tid; idx < 896; idx += 256) {   // pool B chunk 1
                int u = idx & 7, nn = idx >> 3;
                cp16(pbase + SM_BH + SWZ128((uint32_t)(nn * 128 + u * 16)),
                     Wp2 + nn * 64 + 32 + u * 4, 16);
            }
            CP_COMMIT(); CP_WAIT0();
            __syncthreads();
#pragma unroll
            for (int ks = 0; ks < 4; ks++) {   // chunk 1: k64..127
                uint32_t ah[4];
                ldm_x4(ah, pbase + SM_AL + SWZ128((uint32_t)(a_row * 128 + a_kb + ks * 32)));
                uint32_t bloc = SWZ128((uint32_t)(b_row * 128 + b_kb + ks * 32));
                uint32_t bh[7][2];
#pragma unroll
                for (int nt = 0; nt < 7; nt++)
                    ldm_x2(bh[nt], pbase + SM_BH + bloc + (colh * 7 + nt) * 1024);
#pragma unroll
                for (int nt = 0; nt < 7; nt++) mma_fp16(acc2[nt], ah, bh[nt]);
            }
            // z epilogue
#pragma unroll
            for (int nt = 0; nt < 7; nt++) {
                int col = (colh * 7 + nt) * 8 + ec;
                if (col >= HH) continue;
                float b0 = pbias2[col], b1 = pbias2[col + 1];
                float z0 = fmaxf(acc2[nt][0] + b0, 0.f);
                float z1 = fmaxf(acc2[nt][1] + b1, 0.f);
                float z2 = fmaxf(acc2[nt][2] + b0, 0.f);
                float z3 = fmaxf(acc2[nt][3] + b1, 0.f);
                if (glo < n) zout[(size_t)glo * ZP + (col >> 1)] = pack_h(z0, z1);
                if (ghi < n) zout[(size_t)ghi * ZP + (col >> 1)] = pack_h(z2, z3);
            }
            __syncthreads();  // stage ps free before next tile stages into it
        }
    }
}

// ===== mean aggregation over CSR: z packed fp16 (pitch ZP) -> c hi fp16 (pitch HP)
__global__ void aggregate_kernel(const uint32_t* __restrict__ zp,
                                 uint32_t* __restrict__ ch, int n) {
    int w = (blockIdx.x * blockDim.x + threadIdx.x) >> 5;
    int lane = threadIdx.x & 31;
    if (w >= n || lane >= 27) return;
    int s = g_rowptr[w], e = g_rowptr[w + 1];
    float a0 = 0.f, a1 = 0.f, a2 = 0.f, a3 = 0.f;
    int i = s;
    for (; i + 7 < e; i += 8) {
        int cc[8];
#pragma unroll
        for (int q = 0; q < 8; q++) cc[q] = g_col[i + q];
        uint2 u[8];
#pragma unroll
        for (int q = 0; q < 8; q++) u[q] = ((const uint2*)(zp + (size_t)cc[q] * ZP))[lane];
#pragma unroll
        for (int q = 0; q < 8; q++) {
            float2 f0 = __half22float2(*(__half2*)&u[q].x);
            float2 f1 = __half22float2(*(__half2*)&u[q].y);
            a0 += f0.x; a1 += f0.y; a2 += f1.x; a3 += f1.y;
        }
    }
    if (i + 3 < e) {
        int cc[4];
#pragma unroll
        for (int q = 0; q < 4; q++) cc[q] = g_col[i + q];
        uint2 u[4];
#pragma unroll
        for (int q = 0; q < 4; q++) u[q] = ((const uint2*)(zp + (size_t)cc[q] * ZP))[lane];
#pragma unroll
        for (int q = 0; q < 4; q++) {
            float2 f0 = __half22float2(*(__half2*)&u[q].x);
            float2 f1 = __half22float2(*(__half2*)&u[q].y);
            a0 += f0.x; a1 += f0.y; a2 += f1.x; a3 += f1.y;
        }
        i += 4;
    }
    for (; i < e; i++) {
        uint2 u0 = ((const uint2*)(zp + (size_t)g_col[i] * ZP))[lane];
        float2 f0 = __half22float2(*(__half2*)&u0.x);
        float2 f1 = __half22float2(*(__half2*)&u0.y);
        a0 += f0.x; a1 += f0.y; a2 += f1.x; a3 += f1.y;
    }
    float inv = 1.f / (float)max(e - s, 1);
    ch[(size_t)w * HP + lane * 2]     = pack_h(a0 * inv, a1 * inv);
    ch[(size_t)w * HP + lane * 2 + 1] = pack_h(a2 * inv, a3 * inv);
}

// ================= graph readout: block per graph (gids SORTED) ===============
__global__ void readout_graph(const float* __restrict__ h, const int* __restrict__ gids,
                              float* __restrict__ out, int n) {
    __shared__ float part[8][112];
    const int g = blockIdx.x;
    const int tid = threadIdx.x;
    const int wid = tid >> 5;
    const int lane = tid & 31;
    int lo = 0, hi = n;
    while (lo < hi) { int m = (lo + hi) >> 1; if (gids[m] < g) lo = m + 1; else hi = m; }
    const int start = lo;
    hi = n;
    while (lo < hi) { int m = (lo + hi) >> 1; if (gids[m] < g + 1) lo = m + 1; else hi = m; }
    const int end = lo;

    float a0 = 0.f, a1 = 0.f, a2 = 0.f, a3 = 0.f;
    if (lane < 27) {
        for (int r = start + wid; r < end; r += 8) {
            float4 v = ((const float4*)(h + (size_t)r * HH))[lane];
            a0 += v.x; a1 += v.y; a2 += v.z; a3 += v.w;
        }
        part[wid][lane * 4]     = a0;
        part[wid][lane * 4 + 1] = a1;
        part[wid][lane * 4 + 2] = a2;
        part[wid][lane * 4 + 3] = a3;
    }
    __syncthreads();
    if (tid < HH) {
        float sum = 0.f;
#pragma unroll
        for (int wq = 0; wq < 8; wq++) sum += part[wq][tid];
        out[(size_t)g * HH + tid] = sum / fmaxf((float)(end - start), 1.f);
    }
}

// ================= launch =================
extern "C" void kernel_launch(void* const* d_in, const int* in_sizes, int n_in,
                              void* d_out, int out_size) {
    const float* nodes_feat = (const float*)d_in[0];
    const float* W_emb  = (const float*)d_in[4];
    const float* b_emb  = (const float*)d_in[5];
    const float* pool_W = (const float*)d_in[6];
    const float* pool_b = (const float*)d_in[7];
    const float* app_W  = (const float*)d_in[8];
    const float* app_b  = (const float*)d_in[9];
    const int* src  = (const int*)d_in[10];
    const int* dst  = (const int*)d_in[11];
    const int* gids = (const int*)d_in[12];

    const int n = in_sizes[12];
    const int e = in_sizes[10];
    const int in_dim = in_sizes[4] / HH;
    const int n_layers = in_sizes[6] / (HH * HH);
    const int G = out_size / HH;

    float *hP, *zP;
    uint32_t *hhP, *hlP, *chP, *clP, *whP;
    cudaGetSymbolAddress((void**)&hP, g_h);
    cudaGetSymbolAddress((void**)&zP, g_z);
    cudaGetSymbolAddress((void**)&hhP, g_hh);
    cudaGetSymbolAddress((void**)&hlP, g_hl);
    cudaGetSymbolAddress((void**)&chP, g_ch);
    cudaGetSymbolAddress((void**)&clP, g_cl);
    cudaGetSymbolAddress((void**)&whP, g_wh);

    cudaFuncSetAttribute(gemm_tc, cudaFuncAttributeMaxDynamicSharedMemorySize, SM_TOTAL);

    static cudaStream_t s2 = 0;
    static cudaEvent_t evFork = 0, evJoin = 0;
    if (!s2) {
        cudaStreamCreateWithFlags(&s2, cudaStreamNonBlocking);
        cudaEventCreateWithFlags(&evFork, cudaEventDisableTiming);
        cudaEventCreateWithFlags(&evJoin, cudaEventDisableTiming);
    }

    const int KPe = ((in_dim + 63) / 64) * 64;
    const int u_emb = 112 * (KPe >> 1);
    const int u_pool = 112 * 64;
    const int u_app = 112 * 128;
    const int w_total = u_emb + n_layers * (u_pool + u_app);
    const int x_total = n * (KPe >> 1);

    const int tiles = (n + 63) / 64;
    const int pg = tiles < PGRID ? tiles : PGRID;
    int warp_blocks = ((n * 32) + 255) / 256;

    // ---- fork: CSR build on side stream (depends only on src/dst) ----
    cudaEventRecord(evFork, 0);
    cudaStreamWaitEvent(s2, evFork, 0);
    zero_deg_kernel<<<(n + 255) / 256, 256, 0, s2>>>(n);
    hist_kernel<<<(e + 255) / 256, 256, 0, s2>>>(dst, e);
    int nb = (n + SC_CH - 1) / SC_CH;
    scan1_kernel<<<nb, SC_T, 0, s2>>>(n);
    scan2_kernel<<<1, 256, 0, s2>>>(nb);
    scan3_kernel<<<(n + 255) / 256, 256, 0, s2>>>(n);
    fillcsr_kernel<<<(e + 255) / 256, 256, 0, s2>>>(src, dst, e);
    cudaEventRecord(evJoin, s2);

    // ---- main stream: combined prep, then emb fused with pool(0) ----
    prep_all<<<(w_total + x_total + 255) / 256, 256>>>(
        W_emb, in_dim, KPe, pool_W, app_W, n_layers, w_total,
        nodes_feat, in_dim, chP, clP, x_total);
    gemm_tc<<<pg, 256, SM_TOTAL>>>(chP, clP, (const uint32_t*)0, (const uint32_t*)0,
                                   KPe >> 6, KPe >> 1,
                                   whP, KPe >> 1,
                                   b_emb, (float*)0, (const uint32_t*)0, (const uint32_t*)0,
                                   hhP, hlP,
                                   n, KPe, 0, 2,
                                   whP + u_emb, pool_b, (uint32_t*)zP);

    bool joined = false;
    for (int l = 0; l < n_layers; l++) {
        const float* ab = app_b + (size_t)l * HH;
        const uint32_t* aWh = whP + u_emb + n_layers * u_pool + l * u_app;

        if (!joined) { cudaStreamWaitEvent(0, evJoin, 0); joined = true; }
        // c = mean_{u in N(v)} z[u] (z from previous fused kernel)
        aggregate_kernel<<<warp_blocks, 256>>>((const uint32_t*)zP, chP, n);
        // h = h + relu(l2norm([h|c] @ app_W + app_b)); fuse pool(l+1) unless last
        int last = (l == n_layers - 1);
        const uint32_t* nWp = last ? (const uint32_t*)0 : (whP + u_emb + (l + 1) * u_pool);
        const float* nPb = last ? (const float*)0 : (pool_b + (size_t)(l + 1) * HH);
        gemm_tc<<<pg, 256, SM_TOTAL>>>(hhP, hlP, chP, (const uint32_t*)0,
                                       2, HP,
                                       aWh, 128,
                                       ab,
                                       last ? hP : (float*)0,
                                       hhP, hlP,
                                       last ? (uint32_t*)0 : hhP,
                                       last ? (uint32_t*)0 : hlP,
                                       n, 256, 2, 3,
                                       nWp, nPb, (uint32_t*)zP);
    }

    // ---- readout: one block per graph, no atomics (gids sorted) ----
    readout_graph<<<G, 256>>>(hP, gids, (float*)d_out, n);
}